// round 2
// baseline (speedup 1.0000x reference)
#include <cuda_runtime.h>
#include <math.h>
#include <stdint.h>

#define BB    128
#define HID   512
#define G4    2048
#define VOCAB 1000
#define TT    256
#define KDIM  512

typedef unsigned long long ull;

__device__ float g_base[BB * G4];
__device__ float g_P[VOCAB * G4];
__device__ float g_h[2][BB * HID];
__device__ float g_c[BB * HID];
__device__ int   g_token[BB];
__device__ ull   g_pk[BB];

__device__ __forceinline__ ull splat2(float x) {
    ull r; asm("mov.b64 %0, {%1, %1};" : "=l"(r) : "f"(x)); return r;
}
__device__ __forceinline__ void fma2(ull& d, ull a, ull b) {
    asm("fma.rn.f32x2 %0, %1, %2, %0;" : "+l"(d) : "l"(a), "l"(b));
}
__device__ __forceinline__ float2 unpack2(ull x) {
    float lo, hi; asm("mov.b64 {%0, %1}, %2;" : "=f"(lo), "=f"(hi) : "l"(x));
    return make_float2(lo, hi);
}
__device__ __forceinline__ unsigned fkey(float f) {
    unsigned b = __float_as_uint(f);
    return (b & 0x80000000u) ? ~b : (b | 0x80000000u);
}
__device__ __forceinline__ float sigf(float x) { return 1.f / (1.f + expf(-x)); }

__global__ void k_init(const float* __restrict__ ctx, const int* __restrict__ sid) {
    int i = blockIdx.x * 256 + threadIdx.x;          // 65536
    g_h[0][i] = ctx[i];
    g_c[i] = 0.f;
    if (i < BB) { g_token[i] = sid[0]; g_pk[i] = 0ull; }
}

// C[M,2048] = A[M,512] @ W^T (+ b1 + b2). tile 32m x 128n, 256 thr.
__global__ __launch_bounds__(256) void k_gemm(
    const float* __restrict__ A, int M,
    const float* __restrict__ W, int ws_,
    const float* __restrict__ b1, const float* __restrict__ b2, int dst)
{
    __shared__ __align__(16) float As[32][32];
    __shared__ __align__(16) float Ws[32][128];
    float* __restrict__ C = dst ? g_P : g_base;
    const int tid = threadIdx.x, txn = tid & 15, tym = tid >> 4;
    const int m0 = blockIdx.x * 32, n0 = blockIdx.y * 128;
    ull acc[2][4];
#pragma unroll
    for (int m = 0; m < 2; m++)
#pragma unroll
        for (int j = 0; j < 4; j++) acc[m][j] = 0ull;

    for (int k0 = 0; k0 < KDIM; k0 += 32) {
        __syncthreads();
#pragma unroll
        for (int i = 0; i < 4; i++) {
            int idx = i * 256 + tid, r = idx >> 3, kq = idx & 7;
            float4 v = *(const float4*)&W[(size_t)(n0 + r) * ws_ + k0 + kq * 4];
            int sw = r ^ (kq * 4);
            Ws[kq*4+0][sw] = v.x; Ws[kq*4+1][sw] = v.y;
            Ws[kq*4+2][sw] = v.z; Ws[kq*4+3][sw] = v.w;
        }
        {
            int m = tid >> 3, kq = tid & 7, mg = m0 + m;
            float4 v = (mg < M) ? *(const float4*)&A[(size_t)mg * KDIM + k0 + kq * 4]
                                : make_float4(0.f,0.f,0.f,0.f);
            As[kq*4+0][m] = v.x; As[kq*4+1][m] = v.y;
            As[kq*4+2][m] = v.z; As[kq*4+3][m] = v.w;
        }
        __syncthreads();
#pragma unroll
        for (int k = 0; k < 32; k++) {
            int sk = k & 28;
            float2 av = *(const float2*)&As[k][tym * 2];
            ull a0 = splat2(av.x), a1 = splat2(av.y);
            int c1 = (txn * 8) ^ sk;
            ulonglong2 wA = *(const ulonglong2*)&Ws[k][c1];
            ulonglong2 wB = *(const ulonglong2*)&Ws[k][c1 ^ 4];
            fma2(acc[0][0], a0, wA.x); fma2(acc[0][1], a0, wA.y);
            fma2(acc[0][2], a0, wB.x); fma2(acc[0][3], a0, wB.y);
            fma2(acc[1][0], a1, wA.x); fma2(acc[1][1], a1, wA.y);
            fma2(acc[1][2], a1, wB.x); fma2(acc[1][3], a1, wB.y);
        }
    }
    const int n = n0 + txn * 8;
    float bs[8];
#pragma unroll
    for (int i = 0; i < 8; i++) {
        float b = b1 ? b1[n + i] : 0.f;
        if (b2) b += b2[n + i];
        bs[i] = b;
    }
#pragma unroll
    for (int m = 0; m < 2; m++) {
        int mg = m0 + tym * 2 + m;
        if (mg < M) {
            float2 p0 = unpack2(acc[m][0]), p1 = unpack2(acc[m][1]);
            float2 p2 = unpack2(acc[m][2]), p3 = unpack2(acc[m][3]);
            *(float4*)&C[(size_t)mg * G4 + n]     = make_float4(p0.x+bs[0], p0.y+bs[1], p1.x+bs[2], p1.y+bs[3]);
            *(float4*)&C[(size_t)mg * G4 + n + 4] = make_float4(p2.x+bs[4], p2.y+bs[5], p3.x+bs[6], p3.y+bs[7]);
        }
    }
}

// gates = base + P[token] + h@Whh^T, LSTM update. tile 16b x 32u, 256 thr.
__global__ __launch_bounds__(256) void k_step(int rd, const float* __restrict__ Whh)
{
    __shared__ __align__(16) float hs[32][16];
    __shared__ __align__(16) float ws[32][128];
    __shared__ float gt[16][128];
    const int tid = threadIdx.x, tx = tid & 31, ty = tid >> 5;
    const int b0 = blockIdx.x * 16, u0 = blockIdx.y * 32;
    const float* __restrict__ hin = g_h[rd];
    float* __restrict__ hout = g_h[rd ^ 1];

    ull acc[2][2];
    acc[0][0]=acc[0][1]=acc[1][0]=acc[1][1]=0ull;

    for (int k0 = 0; k0 < KDIM; k0 += 32) {
        __syncthreads();
#pragma unroll
        for (int i = 0; i < 4; i++) {
            int idx = i * 256 + tid, r = idx >> 3, kq = idx & 7;
            int row = ((r >> 5) * HID) + u0 + (r & 31);
            float4 v = *(const float4*)&Whh[(size_t)row * KDIM + k0 + kq * 4];
            int sw = r ^ (kq * 4);
            ws[kq*4+0][sw] = v.x; ws[kq*4+1][sw] = v.y;
            ws[kq*4+2][sw] = v.z; ws[kq*4+3][sw] = v.w;
        }
        if (tid < 128) {
            int b = tid >> 3, kq = tid & 7;
            float4 v = *(const float4*)&hin[(size_t)(b0 + b) * HID + k0 + kq * 4];
            hs[kq*4+0][b] = v.x; hs[kq*4+1][b] = v.y;
            hs[kq*4+2][b] = v.z; hs[kq*4+3][b] = v.w;
        }
        __syncthreads();
#pragma unroll
        for (int k = 0; k < 32; k++) {
            int sk = k & 28;
            float2 av = *(const float2*)&hs[k][ty * 2];
            ull a0 = splat2(av.x), a1 = splat2(av.y);
            ulonglong2 w = *(const ulonglong2*)&ws[k][(tx * 4) ^ sk];
            fma2(acc[0][0], a0, w.x); fma2(acc[0][1], a0, w.y);
            fma2(acc[1][0], a1, w.x); fma2(acc[1][1], a1, w.y);
        }
    }
    {
        const int g = tx >> 3, uu0 = (tx & 7) * 4;
        const int coln = g * HID + u0 + uu0;
#pragma unroll
        for (int m = 0; m < 2; m++) {
            int b = ty * 2 + m, bg = b0 + b;
            int tok = g_token[bg];
            float4 bb = *(const float4*)&g_base[(size_t)bg * G4 + coln];
            float4 pp = *(const float4*)&g_P[(size_t)tok * G4 + coln];
            float2 x0 = unpack2(acc[m][0]), x1 = unpack2(acc[m][1]);
            *(float4*)&gt[b][tx * 4] = make_float4(
                x0.x+bb.x+pp.x, x0.y+bb.y+pp.y, x1.x+bb.z+pp.z, x1.y+bb.w+pp.w);
        }
    }
    __syncthreads();
#pragma unroll
    for (int j = 0; j < 2; j++) {
        int it = j * 256 + tid, b = it >> 5, u = it & 31;
        float gi = gt[b][u], gf = gt[b][32+u], gg = gt[b][64+u], go = gt[b][96+u];
        int bg = b0 + b, ug = u0 + u;
        float co = g_c[bg * HID + ug];
        float cn = sigf(gf) * co + sigf(gi) * tanhf(gg);
        g_c[bg * HID + ug] = cn;
        hout[bg * HID + ug] = sigf(go) * tanhf(cn);
    }
}

// logits + argmax. tile 16b x 64v, 128 thr.
__global__ __launch_bounds__(128) void k_logits(int rd, const float* __restrict__ Wout,
                                                const float* __restrict__ bout,
                                                float* __restrict__ out, int t)
{
    __shared__ __align__(16) float hs[32][16];
    __shared__ __align__(16) float ws[32][64];
    __shared__ ull spk[16];
    const int tid = threadIdx.x, tx = tid & 15, ty = tid >> 4;
    const int b0 = blockIdx.x * 16, v0 = blockIdx.y * 64;
    const float* __restrict__ hin = g_h[rd];
    if (tid < 16) spk[tid] = 0ull;

    ull acc[2][2];
    acc[0][0]=acc[0][1]=acc[1][0]=acc[1][1]=0ull;

    for (int k0 = 0; k0 < KDIM; k0 += 32) {
        __syncthreads();
#pragma unroll
        for (int i = 0; i < 4; i++) {
            int idx = i * 128 + tid, r = idx >> 3, kq = idx & 7, vg = v0 + r;
            float4 v = (vg < VOCAB) ? *(const float4*)&Wout[(size_t)vg * KDIM + k0 + kq * 4]
                                    : make_float4(0.f,0.f,0.f,0.f);
            int sw = r ^ (kq * 4);
            ws[kq*4+0][sw] = v.x; ws[kq*4+1][sw] = v.y;
            ws[kq*4+2][sw] = v.z; ws[kq*4+3][sw] = v.w;
        }
        {
            int b = tid >> 3, kq = tid & 7;
            float4 v = *(const float4*)&hin[(size_t)(b0 + b) * HID + k0 + kq * 4];
            hs[kq*4+0][b] = v.x; hs[kq*4+1][b] = v.y;
            hs[kq*4+2][b] = v.z; hs[kq*4+3][b] = v.w;
        }
        __syncthreads();
#pragma unroll
        for (int k = 0; k < 32; k++) {
            int sk = k & 28;
            float2 av = *(const float2*)&hs[k][ty * 2];
            ull a0 = splat2(av.x), a1 = splat2(av.y);
            ulonglong2 w = *(const ulonglong2*)&ws[k][(tx * 4) ^ sk];
            fma2(acc[0][0], a0, w.x); fma2(acc[0][1], a0, w.y);
            fma2(acc[1][0], a1, w.x); fma2(acc[1][1], a1, w.y);
        }
    }
    int v = v0 + tx * 4;
    ull best[2] = {0ull, 0ull};
    if (v < VOCAB) {
        float4 bo = *(const float4*)&bout[v];
#pragma unroll
        for (int m = 0; m < 2; m++) {
            int bg = b0 + ty * 2 + m;
            float2 x0 = unpack2(acc[m][0]), x1 = unpack2(acc[m][1]);
            float4 o = make_float4(x0.x+bo.x, x0.y+bo.y, x1.x+bo.z, x1.y+bo.w);
            *(float4*)&out[((size_t)bg * TT + t) * VOCAB + v] = o;
            ull p;
            p = ((ull)fkey(o.x) << 32) | (unsigned)(~(v+0)); if (p > best[m]) best[m] = p;
            p = ((ull)fkey(o.y) << 32) | (unsigned)(~(v+1)); if (p > best[m]) best[m] = p;
            p = ((ull)fkey(o.z) << 32) | (unsigned)(~(v+2)); if (p > best[m]) best[m] = p;
            p = ((ull)fkey(o.w) << 32) | (unsigned)(~(v+3)); if (p > best[m]) best[m] = p;
        }
    }
    atomicMax(&spk[ty * 2 + 0], best[0]);
    atomicMax(&spk[ty * 2 + 1], best[1]);
    __syncthreads();
    if (tid < 16) atomicMax(&g_pk[b0 + tid], spk[tid]);
}

__global__ void k_token() {
    int b = threadIdx.x;
    if (b < BB) {
        g_token[b] = (int)(~(unsigned)(g_pk[b] & 0xFFFFFFFFull));
        g_pk[b] = 0ull;
    }
}

__global__ void k_final(float* __restrict__ dst) {
    int i = blockIdx.x * 256 + threadIdx.x;          // 65536
    dst[i] = g_h[0][i];
    dst[BB * HID + i] = g_c[i];
}

extern "C" void kernel_launch(void* const* d_in, const int* in_sizes, int n_in,
                              void* d_out, int out_size) {
    const float* ctx  = (const float*)d_in[0];
    const float* emb  = (const float*)d_in[1];
    const float* Wih  = (const float*)d_in[2];
    const float* bih  = (const float*)d_in[3];
    const float* Whh  = (const float*)d_in[4];
    const float* bhh  = (const float*)d_in[5];
    const float* Wout = (const float*)d_in[6];
    const float* bout = (const float*)d_in[7];
    const int*   sid  = (const int*)d_in[8];
    float* out = (float*)d_out;

    k_init<<<256, 256>>>(ctx, sid);
    k_gemm<<<dim3(4, 16), 256>>>(ctx, BB, Wih, 1024, bih, bhh, 0);
    k_gemm<<<dim3(32, 16), 256>>>(emb, VOCAB, Wih + 512, 1024, (const float*)0, (const float*)0, 1);

    for (int t = 0; t < TT; t++) {
        int rd = t & 1;
        k_step<<<dim3(8, 16), 256>>>(rd, Whh);
        k_logits<<<dim3(8, 16), 128>>>(rd ^ 1, Wout, bout, out, t);
        k_token<<<1, 128>>>();
    }
    long long need = (long long)BB * TT * VOCAB + 2LL * BB * HID;
    if ((long long)out_size >= need)
        k_final<<<256, 256>>>(out + (size_t)BB * TT * VOCAB);
}

// round 4
// speedup vs baseline: 1.1492x; 1.1492x over previous
#include <cuda_runtime.h>
#include <math.h>
#include <stdint.h>

#define BB    128
#define HID   512
#define G4    2048
#define VOCAB 1000
#define TT    256
#define KDIM  512
#define NBLK  128
#define NTHR  512

typedef unsigned long long ull;

__device__ float g_base[BB * G4];
__device__ float g_P[VOCAB * G4];
__device__ float g_h[2][BB * HID];
__device__ float g_c[BB * HID];
__device__ ull   g_pk[2][BB];
__device__ unsigned g_cnt;
__device__ volatile unsigned g_gen;

__device__ __forceinline__ ull splat2(float x) {
    ull r; asm("mov.b64 %0, {%1, %1};" : "=l"(r) : "f"(x)); return r;
}
__device__ __forceinline__ void fma2(ull& d, ull a, ull b) {
    asm("fma.rn.f32x2 %0, %1, %2, %0;" : "+l"(d) : "l"(a), "l"(b));
}
__device__ __forceinline__ float2 unpack2(ull x) {
    float lo, hi; asm("mov.b64 {%0, %1}, %2;" : "=f"(lo), "=f"(hi) : "l"(x));
    return make_float2(lo, hi);
}
__device__ __forceinline__ unsigned fkey(float f) {
    unsigned b = __float_as_uint(f);
    return (b & 0x80000000u) ? ~b : (b | 0x80000000u);
}
__device__ __forceinline__ float sigf(float x) { return 1.f / (1.f + expf(-x)); }

__device__ __forceinline__ void gsync() {
    __syncthreads();
    if (threadIdx.x == 0) {
        unsigned g = g_gen;
        __threadfence();
        if (atomicAdd(&g_cnt, 1u) == NBLK - 1) {
            g_cnt = 0;
            __threadfence();
            g_gen = g + 1;
        } else {
            while (g_gen == g) { }
        }
    }
    __syncthreads();
}

__global__ void k_init(const float* __restrict__ ctx, const int* __restrict__ sid) {
    int i = blockIdx.x * 256 + threadIdx.x;          // 65536
    g_h[0][i] = ctx[i];
    g_c[i] = 0.f;
    if (i < BB) {
        g_pk[0][i] = 0ull;
        g_pk[1][i] = (ull)(unsigned)(~(unsigned)sid[0]);   // decodes to start_id
    }
    if (i == 0) { g_cnt = 0u; g_gen = 0u; }
}

// one-time precompute: C[M,2048] = A[M,512] @ W^T (+b1+b2). tile 32m x 128n.
__global__ __launch_bounds__(256) void k_gemm(
    const float* __restrict__ A, int M,
    const float* __restrict__ W, int ws_,
    const float* __restrict__ b1, const float* __restrict__ b2, int dst)
{
    __shared__ __align__(16) float As[32][32];
    __shared__ __align__(16) float Ws[32][128];
    float* __restrict__ C = dst ? g_P : g_base;
    const int tid = threadIdx.x, txn = tid & 15, tym = tid >> 4;
    const int m0 = blockIdx.x * 32, n0 = blockIdx.y * 128;
    ull acc[2][4];
#pragma unroll
    for (int m = 0; m < 2; m++)
#pragma unroll
        for (int j = 0; j < 4; j++) acc[m][j] = 0ull;

    for (int k0 = 0; k0 < KDIM; k0 += 32) {
        __syncthreads();
#pragma unroll
        for (int i = 0; i < 4; i++) {
            int idx = i * 256 + tid, r = idx >> 3, kq = idx & 7;
            float4 v = *(const float4*)&W[(size_t)(n0 + r) * ws_ + k0 + kq * 4];
            int sw = r ^ (kq * 4);
            Ws[kq*4+0][sw] = v.x; Ws[kq*4+1][sw] = v.y;
            Ws[kq*4+2][sw] = v.z; Ws[kq*4+3][sw] = v.w;
        }
        {
            int m = tid >> 3, kq = tid & 7, mg = m0 + m;
            float4 v = (mg < M) ? *(const float4*)&A[(size_t)mg * KDIM + k0 + kq * 4]
                                : make_float4(0.f,0.f,0.f,0.f);
            As[kq*4+0][m] = v.x; As[kq*4+1][m] = v.y;
            As[kq*4+2][m] = v.z; As[kq*4+3][m] = v.w;
        }
        __syncthreads();
#pragma unroll
        for (int k = 0; k < 32; k++) {
            int sk = k & 28;
            float2 av = *(const float2*)&As[k][tym * 2];
            ull a0 = splat2(av.x), a1 = splat2(av.y);
            int c1 = (txn * 8) ^ sk;
            ulonglong2 wA = *(const ulonglong2*)&Ws[k][c1];
            ulonglong2 wB = *(const ulonglong2*)&Ws[k][c1 ^ 4];
            fma2(acc[0][0], a0, wA.x); fma2(acc[0][1], a0, wA.y);
            fma2(acc[0][2], a0, wB.x); fma2(acc[0][3], a0, wB.y);
            fma2(acc[1][0], a1, wA.x); fma2(acc[1][1], a1, wA.y);
            fma2(acc[1][2], a1, wB.x); fma2(acc[1][3], a1, wB.y);
        }
    }
    const int n = n0 + txn * 8;
    float bs[8];
#pragma unroll
    for (int i = 0; i < 8; i++) {
        float b = b1 ? b1[n + i] : 0.f;
        if (b2) b += b2[n + i];
        bs[i] = b;
    }
#pragma unroll
    for (int m = 0; m < 2; m++) {
        int mg = m0 + tym * 2 + m;
        if (mg < M) {
            float2 p0 = unpack2(acc[m][0]), p1 = unpack2(acc[m][1]);
            float2 p2 = unpack2(acc[m][2]), p3 = unpack2(acc[m][3]);
            *(float4*)&C[(size_t)mg * G4 + n]     = make_float4(p0.x+bs[0], p0.y+bs[1], p1.x+bs[2], p1.y+bs[3]);
            *(float4*)&C[(size_t)mg * G4 + n + 4] = make_float4(p2.x+bs[4], p2.y+bs[5], p3.x+bs[6], p3.y+bs[7]);
        }
    }
}

// 16 b-values at step k live at hs[k*16 + 4*(bq^(k&3)) ..], bq = b>>2 (XOR swizzle)
#define DOJ(WV, J) { ull wj = splat2(WV);                                              \
    { ulonglong2 hp = *(const ulonglong2*)&hs[kb + (J)*16 + 4*(0^(J))];                \
      fma2(acc[0], wj, hp.x); fma2(acc[1], wj, hp.y); }                                \
    { ulonglong2 hp = *(const ulonglong2*)&hs[kb + (J)*16 + 4*(1^(J))];                \
      fma2(acc[2], wj, hp.x); fma2(acc[3], wj, hp.y); }                                \
    { ulonglong2 hp = *(const ulonglong2*)&hs[kb + (J)*16 + 4*(2^(J))];                \
      fma2(acc[4], wj, hp.x); fma2(acc[5], wj, hp.y); }                                \
    { ulonglong2 hp = *(const ulonglong2*)&hs[kb + (J)*16 + 4*(3^(J))];                \
      fma2(acc[6], wj, hp.x); fma2(acc[7], wj, hp.y); } }

__global__ __launch_bounds__(NTHR, 1) void k_run(
    const float* __restrict__ Whh, const float* __restrict__ Wout,
    const float* __restrict__ bout, float* __restrict__ out, int do_hc)
{
    __shared__ __align__(16) float hs[8192];     // 16b x 512k staged h (union: reduce buf)
    __shared__ float gt[128 * 17];               // per-phase result exchange
    const int tid = threadIdx.x;
    const int bid = blockIdx.x;
    const int b0 = (bid >> 4) * 16;
    const int u0 = (bid & 15) * 32;
    const int v0 = (bid & 15) * 64;

    for (int t = 0; t < TT; t++) {
        const int rd = t & 1;

        // ================= Phase A: gates + LSTM =================
        {   // stage h[rd] -> hs (k-major, swizzled)
            const float* hsrc = g_h[rd];
            int bq = tid >> 7;
#pragma unroll
            for (int i = 0; i < 4; i++) {
                int k = (tid & 127) + 128 * i;
                float4 v;
                v.x = hsrc[(b0 + bq*4 + 0) * HID + k];
                v.y = hsrc[(b0 + bq*4 + 1) * HID + k];
                v.z = hsrc[(b0 + bq*4 + 2) * HID + k];
                v.w = hsrc[(b0 + bq*4 + 3) * HID + k];
                *(float4*)&hs[k * 16 + 4 * (bq ^ (k & 3))] = v;
            }
        }
        __syncthreads();
        {
            const int r = tid & 127, q = tid >> 7;        // 128 gate-rows x 4 K-quarters
            const int rowg = (r >> 5) * HID + u0 + (r & 31);
            const float* wp = Whh + (size_t)rowg * KDIM + q * 128;
            ull acc[8];
#pragma unroll
            for (int i = 0; i < 8; i++) acc[i] = 0ull;
#pragma unroll 4
            for (int kk = 0; kk < 128; kk += 4) {
                float4 w = *(const float4*)(wp + kk);
                const int kb = (q * 128 + kk) * 16;
                DOJ(w.x, 0) DOJ(w.y, 1) DOJ(w.z, 2) DOJ(w.w, 3)
            }
            __syncthreads();
            float* red = hs;                               // union: reuse h tile
            if (q) {
                int base = (q - 1) * 2176 + r * 17;
#pragma unroll
                for (int i = 0; i < 8; i++) {
                    float2 p = unpack2(acc[i]);
                    red[base + 2*i] = p.x; red[base + 2*i + 1] = p.y;
                }
            }
            __syncthreads();
            if (q == 0) {
                float fa[16];
#pragma unroll
                for (int i = 0; i < 8; i++) {
                    float2 p = unpack2(acc[i]);
                    fa[2*i] = p.x; fa[2*i + 1] = p.y;
                }
#pragma unroll
                for (int qq = 0; qq < 3; qq++) {
                    int base = qq * 2176 + r * 17;
#pragma unroll
                    for (int b = 0; b < 16; b++) fa[b] += red[base + b];
                }
#pragma unroll
                for (int b = 0; b < 16; b++) gt[r * 17 + b] = fa[b];
            }
        }
        __syncthreads();
        {   // LSTM elementwise: thread -> (b, u)
            const int b = tid >> 5, ul = tid & 31;
            const int bg = b0 + b, col = u0 + ul;
            const int tok = (int)(~(unsigned)g_pk[rd ^ 1][bg]);
            const float* bp = g_base + (size_t)bg * G4;
            const float* pp = g_P + (size_t)tok * G4;
            float gv[4];
#pragma unroll
            for (int g = 0; g < 4; g++)
                gv[g] = gt[(g * 32 + ul) * 17 + b] + bp[g * HID + col] + pp[g * HID + col];
            float c = g_c[bg * HID + col];
            float cn = sigf(gv[1]) * c + sigf(gv[0]) * tanhf(gv[2]);
            g_c[bg * HID + col] = cn;
            g_h[rd ^ 1][bg * HID + col] = sigf(gv[3]) * tanhf(cn);
        }
        if ((bid & 15) == 0 && tid < 16) g_pk[rd][b0 + tid] = 0ull;  // consumed last step
        gsync();

        // ================= Phase B: logits + argmax =================
        {   // stage h[rd^1]
            const float* hsrc = g_h[rd ^ 1];
            int bq = tid >> 7;
#pragma unroll
            for (int i = 0; i < 4; i++) {
                int k = (tid & 127) + 128 * i;
                float4 v;
                v.x = hsrc[(b0 + bq*4 + 0) * HID + k];
                v.y = hsrc[(b0 + bq*4 + 1) * HID + k];
                v.z = hsrc[(b0 + bq*4 + 2) * HID + k];
                v.w = hsrc[(b0 + bq*4 + 3) * HID + k];
                *(float4*)&hs[k * 16 + 4 * (bq ^ (k & 3))] = v;
            }
        }
        __syncthreads();
        {
            const int r = tid & 63, q = tid >> 6;          // 64 vocab rows x 8 K-eighths
            const int v = v0 + r;
            const bool vok = (v < VOCAB);
            ull acc[8];
#pragma unroll
            for (int i = 0; i < 8; i++) acc[i] = 0ull;
            if (vok) {
                const float* wp = Wout + (size_t)v * KDIM + q * 64;
#pragma unroll 4
                for (int kk = 0; kk < 64; kk += 4) {
                    float4 w = *(const float4*)(wp + kk);
                    const int kb = (q * 64 + kk) * 16;
                    DOJ(w.x, 0) DOJ(w.y, 1) DOJ(w.z, 2) DOJ(w.w, 3)
                }
            }
            __syncthreads();
            float* red = hs;
            if (q) {
                int base = (q - 1) * 1088 + r * 17;
#pragma unroll
                for (int i = 0; i < 8; i++) {
                    float2 p = unpack2(acc[i]);
                    red[base + 2*i] = p.x; red[base + 2*i + 1] = p.y;
                }
            }
            __syncthreads();
            if (q == 0) {
                float fa[16];
#pragma unroll
                for (int i = 0; i < 8; i++) {
                    float2 p = unpack2(acc[i]);
                    fa[2*i] = p.x; fa[2*i + 1] = p.y;
                }
#pragma unroll
                for (int qq = 0; qq < 7; qq++) {
                    int base = qq * 1088 + r * 17;
#pragma unroll
                    for (int b = 0; b < 16; b++) fa[b] += red[base + b];
                }
                float bo = vok ? bout[v] : 0.f;
#pragma unroll
                for (int b = 0; b < 16; b++) gt[r * 17 + b] = fa[b] + bo;
            }
        }
        __syncthreads();
        {   // coalesced logits store + fused argmax (warp-reduced)
            const int vl = tid & 63;
            const int vg = v0 + vl;
#pragma unroll
            for (int h = 0; h < 2; h++) {
                const int b = (tid >> 6) + 8 * h;          // uniform per warp
                float val = gt[vl * 17 + b];
                ull pk = 0ull;
                if (vg < VOCAB) {
                    out[((size_t)(b0 + b) * TT + t) * VOCAB + vg] = val;
                    pk = ((ull)fkey(val) << 32) | (unsigned)(~vg);
                }
#pragma unroll
                for (int s = 16; s; s >>= 1) {
                    ull o = __shfl_down_sync(0xffffffffu, pk, s);
                    if (o > pk) pk = o;
                }
                if ((tid & 31) == 0 && pk) atomicMax(&g_pk[rd][b0 + b], pk);
            }
        }
        gsync();
    }

    if (do_hc) {   // final h, c
        float* dst = out + (size_t)BB * TT * VOCAB;
        int i = bid * NTHR + tid;                          // 65536
        dst[i] = g_h[0][i];
        dst[BB * HID + i] = g_c[i];
    }
}

extern "C" void kernel_launch(void* const* d_in, const int* in_sizes, int n_in,
                              void* d_out, int out_size) {
    const float* ctx  = (const float*)d_in[0];
    const float* emb  = (const float*)d_in[1];
    const float* Wih  = (const float*)d_in[2];
    const float* bih  = (const float*)d_in[3];
    const float* Whh  = (const float*)d_in[4];
    const float* bhh  = (const float*)d_in[5];
    const float* Wout = (const float*)d_in[6];
    const float* bout = (const float*)d_in[7];
    const int*   sid  = (const int*)d_in[8];
    float* out = (float*)d_out;

    k_init<<<256, 256>>>(ctx, sid);
    k_gemm<<<dim3(4, 16), 256>>>(ctx, BB, Wih, 1024, bih, bhh, 0);
    k_gemm<<<dim3(32, 16), 256>>>(emb, VOCAB, Wih + 512, 1024, (const float*)0, (const float*)0, 1);

    long long need = (long long)BB * TT * VOCAB + 2LL * BB * HID;
    int do_hc = ((long long)out_size >= need) ? 1 : 0;
    k_run<<<NBLK, NTHR>>>(Whh, Wout, bout, out, do_hc);
}